// round 11
// baseline (speedup 1.0000x reference)
#include <cuda_runtime.h>
#include <math.h>
#include <stdint.h>

#define HID 128
#define NMAX 10000
#define EMAX 300000
#define DINP 448          // padded H width (441 -> 448)

// ---------------- device-global scratch (no allocs) ----------------
__device__ __align__(128) float g_Vl[(size_t)NMAX * 96];
__device__ __align__(128) float g_Ve[(size_t)EMAX * 96];
__device__ __align__(128) float g_H [(size_t)EMAX * DINP];
__device__ __align__(128) float g_Y1[(size_t)EMAX * HID];
__device__ __align__(128) float g_Y2[(size_t)EMAX * HID];
__device__ __align__(128) float g_Bfin[256 * 128];
__device__ __align__(128) float g_bfin[128];
__device__ float g_stats[512];   // layer {sum[128], sumsq[128]} x2
__device__ float g_coef [512];   // layer {a[128],   s[128]} x2

__device__ __forceinline__ float rtf32(float x) {
    uint32_t u;
    asm("cvt.rna.tf32.f32 %0, %1;" : "=r"(u) : "f"(x));
    return __uint_as_float(u);
}

// ---------------- small helpers ----------------
__global__ void zero_stats_kernel() {
    if (threadIdx.x < 512) g_stats[threadIdx.x] = 0.f;
}

__global__ void bn_coef_kernel(int layer, const float* __restrict__ g,
                               const float* __restrict__ be, float invM) {
    int c = threadIdx.x;
    float m = g_stats[layer * 256 + c] * invM;
    float v = g_stats[layer * 256 + 128 + c] * invM - m * m;
    float a = g[c] * rsqrtf(v + 1e-5f);
    g_coef[layer * 256 + c]       = a;
    g_coef[layer * 256 + 128 + c] = be[c] - m * a;
}

__global__ void prep_final_kernel(const float* __restrict__ W3, const float* __restrict__ Wm,
                                  const float* __restrict__ b3, const float* __restrict__ bm) {
    __shared__ float rowv[128];
    int j = threadIdx.x;
    int k = blockIdx.x;
    if (k < 128) {
        rowv[j] = W3[k * 128 + j];
        __syncthreads();
        float s = 0.f;
#pragma unroll 8
        for (int t = 0; t < 128; t++) s += rowv[t] * Wm[(128 + t) * 128 + j];
        g_Bfin[k * 128 + j]         = s;                 // W3 @ Wm_bot
        g_Bfin[(128 + k) * 128 + j] = Wm[k * 128 + j];   // Wm_top
    } else {
        rowv[j] = b3[j];
        __syncthreads();
        float s = 0.f;
#pragma unroll 8
        for (int t = 0; t < 128; t++) s += rowv[t] * Wm[(128 + t) * 128 + j];
        g_bfin[j] = s + bm[j];
    }
}

// ---------------- per-edge geometric features (one warp per edge) ----------------
__global__ void edge_feat_kernel(const float* __restrict__ Ve, const float* __restrict__ Vl,
                                 const int* __restrict__ eidx, const float* __restrict__ rot,
                                 const float* __restrict__ trans, float* __restrict__ H, int E) {
    int w    = (blockIdx.x * blockDim.x + threadIdx.x) >> 5;
    int lane = threadIdx.x & 31;
    if (w >= E) return;
    const size_t e = (size_t)w;

    int s = eidx[e];
    int d = eidx[(size_t)E + e];

    float R0 = __ldg(rot + e * 9 + 0), R1 = __ldg(rot + e * 9 + 1), R2 = __ldg(rot + e * 9 + 2);
    float R3 = __ldg(rot + e * 9 + 3), R4 = __ldg(rot + e * 9 + 4), R5 = __ldg(rot + e * 9 + 5);
    float R6 = __ldg(rot + e * 9 + 6), R7 = __ldg(rot + e * 9 + 7), R8 = __ldg(rot + e * 9 + 8);
    float t0 = __ldg(trans + e * 3 + 0), t1 = __ldg(trans + e * 3 + 1), t2 = __ldg(trans + e * 3 + 2);

    const float* ve = Ve + e * 96 + lane * 3;
    float ve0 = ve[0], ve1 = ve[1], ve2 = ve[2];
    const float* vs = Vl + (size_t)s * 96 + lane * 3;
    float vs0 = vs[0], vs1 = vs[1], vs2 = vs[2];
    const float* vd = Vl + (size_t)d * 96 + lane * 3;
    float vd0 = vd[0], vd1 = vd[1], vd2 = vd[2];

    float* h = H + e * (size_t)DINP;
    h[lane * 3 + 0] = ve0;  h[lane * 3 + 1] = ve1;  h[lane * 3 + 2] = ve2;
    h[96 + lane * 3 + 0] = vs0;  h[96 + lane * 3 + 1] = vs1;  h[96 + lane * 3 + 2] = vs2;
    h[192 + lane * 3 + 0] = R0 * ve0 + R1 * ve1 + R2 * ve2 + t0;
    h[192 + lane * 3 + 1] = R3 * ve0 + R4 * ve1 + R5 * ve2 + t1;
    h[192 + lane * 3 + 2] = R6 * ve0 + R7 * ve1 + R8 * ve2 + t2;
    float rs0 = R0 * vs0 + R1 * vs1 + R2 * vs2;
    float rs1 = R3 * vs0 + R4 * vs1 + R5 * vs2;
    float rs2 = R6 * vs0 + R7 * vs1 + R8 * vs2;
    h[288 + lane * 3 + 0] = rs0 + t0;
    h[288 + lane * 3 + 1] = rs1 + t1;
    h[288 + lane * 3 + 2] = rs2 + t2;
    h[409 + lane] = vd0 * rs0 + vd1 * rs1 + vd2 * rs2;
    if (lane < 9) h[384 + lane] = __ldg(rot + e * 9 + lane);
    if (lane < 16) {
        float nrm = sqrtf(t0 * t0 + t1 * t1 + t2 * t2);
        float c = (50.f / 15.f) * (float)lane;
        float z = (nrm - c) * (1.f / 3.125f);
        h[393 + lane] = expf(-z * z);
    }
    if (lane < 7) h[441 + lane] = 0.f;   // pad to 448
}

// ---------------- tf32 mma.sync GEMM: 128x128x16 tile, 8 warps, double-buffered ----------------
// MODE 0: C = A@B + bias                                        (projections)
// MODE 1: C = A@B + bias, + BN stats layer0                     (GEMM1, A=H padded)
// MODE 2: C = relu(a0*A+s0)@B + bias, + BN stats layer1         (GEMM2, A=Y1)
// MODE 3: C = [relu(a1*A+s1) | A2]@B + bias                     (final, A=Y2, A2=h_E)
template <int MODE>
__global__ void __launch_bounds__(256, 2)
gemm_mma(const float* __restrict__ A, const float* __restrict__ A2,
         const float* __restrict__ B, const float* __restrict__ bias,
         float* __restrict__ C, int M, int K, int KB, int Nact, int lda) {
    __shared__ float As[2][128][20];
    __shared__ float Bs[2][16][136];
    __shared__ float sh_sum[128];
    __shared__ float sh_sq[128];
    __shared__ float s_coef[256];

    const int tid  = threadIdx.x;
    const int wid  = tid >> 5;
    const int lane = tid & 31;
    const int gid  = lane >> 2;   // group id 0..7
    const int tig  = lane & 3;    // thread-in-group 0..3
    const int row0 = blockIdx.x * 128;
    const int m_base = (wid >> 2) * 64;   // 0 or 64
    const int n_base = (wid & 3) * 32;    // 0,32,64,96

    if (MODE == 1 || MODE == 2) {
        if (tid < 128) { sh_sum[tid] = 0.f; sh_sq[tid] = 0.f; }
    }
    if (MODE >= 2) {
        const float* cf = g_coef + ((MODE == 2) ? 0 : 256);
        if (tid < 256) s_coef[tid] = cf[tid];
    }
    // REQUIRED: loadA below reads s_coef written by other threads (MODE>=2).
    __syncthreads();

    auto loadA = [&](int k0, float4 va[2]) {
#pragma unroll
        for (int j = 0; j < 2; j++) {
            int idx = tid + 256 * j;
            int r = idx >> 2, kq = idx & 3;
            int k = k0 + kq * 4;
            int grow = row0 + r;
            float4 v = make_float4(0.f, 0.f, 0.f, 0.f);
            if (grow < M) {
                if (MODE == 3 && k >= 128) {
                    v = *(const float4*)(A2 + (size_t)grow * 128 + (k - 128));
                } else {
                    v = *(const float4*)(A + (size_t)grow * lda + k);
                    if (MODE >= 2) {
                        v.x = fmaxf(fmaf(s_coef[k + 0], v.x, s_coef[128 + k + 0]), 0.f);
                        v.y = fmaxf(fmaf(s_coef[k + 1], v.y, s_coef[128 + k + 1]), 0.f);
                        v.z = fmaxf(fmaf(s_coef[k + 2], v.z, s_coef[128 + k + 2]), 0.f);
                        v.w = fmaxf(fmaf(s_coef[k + 3], v.w, s_coef[128 + k + 3]), 0.f);
                    }
                }
            }
            v.x = rtf32(v.x); v.y = rtf32(v.y); v.z = rtf32(v.z); v.w = rtf32(v.w);
            va[j] = v;
        }
    };
    auto loadB = [&](int k0, float4 vb[2]) {
#pragma unroll
        for (int j = 0; j < 2; j++) {
            int idx = tid + 256 * j;
            int kr = idx >> 5, nq = idx & 31;
            int k = k0 + kr;
            int n = nq * 4;
            float4 v = make_float4(0.f, 0.f, 0.f, 0.f);
            if (k < KB && n < Nact)
                v = *(const float4*)(B + (size_t)k * Nact + n);
            v.x = rtf32(v.x); v.y = rtf32(v.y); v.z = rtf32(v.z); v.w = rtf32(v.w);
            vb[j] = v;
        }
    };
    auto stsAB = [&](int buf, const float4 va[2], const float4 vb[2]) {
#pragma unroll
        for (int j = 0; j < 2; j++) {
            int idx = tid + 256 * j;
            *(float4*)&As[buf][idx >> 2][(idx & 3) * 4] = va[j];
            *(float4*)&Bs[buf][idx >> 5][(idx & 31) * 4] = vb[j];
        }
    };

    float c[4][4][4];
#pragma unroll
    for (int mf = 0; mf < 4; mf++)
#pragma unroll
        for (int nf = 0; nf < 4; nf++)
#pragma unroll
            for (int j = 0; j < 4; j++) c[mf][nf][j] = 0.f;

    const int nk = K >> 4;
    float4 va[2], vb[2];
    loadA(0, va);
    loadB(0, vb);
    stsAB(0, va, vb);
    __syncthreads();

    for (int t = 0; t < nk; t++) {
        const int cur = t & 1;
        if (t + 1 < nk) {
            loadA((t + 1) << 4, va);
            loadB((t + 1) << 4, vb);
        }
        // ---- mma on buffer cur: two k=8 halves ----
#pragma unroll
        for (int kk = 0; kk < 16; kk += 8) {
            uint32_t af[4][4];
#pragma unroll
            for (int mf = 0; mf < 4; mf++) {
                int mr = m_base + mf * 16 + gid;
                af[mf][0] = __float_as_uint(As[cur][mr    ][kk + tig    ]);
                af[mf][1] = __float_as_uint(As[cur][mr + 8][kk + tig    ]);
                af[mf][2] = __float_as_uint(As[cur][mr    ][kk + tig + 4]);
                af[mf][3] = __float_as_uint(As[cur][mr + 8][kk + tig + 4]);
            }
            uint32_t bf[4][2];
#pragma unroll
            for (int nf = 0; nf < 4; nf++) {
                int nc = n_base + nf * 8 + gid;
                bf[nf][0] = __float_as_uint(Bs[cur][kk + tig    ][nc]);
                bf[nf][1] = __float_as_uint(Bs[cur][kk + tig + 4][nc]);
            }
#pragma unroll
            for (int mf = 0; mf < 4; mf++)
#pragma unroll
                for (int nf = 0; nf < 4; nf++) {
                    asm volatile(
                        "mma.sync.aligned.m16n8k8.row.col.f32.tf32.tf32.f32 "
                        "{%0,%1,%2,%3}, {%4,%5,%6,%7}, {%8,%9}, {%0,%1,%2,%3};"
                        : "+f"(c[mf][nf][0]), "+f"(c[mf][nf][1]),
                          "+f"(c[mf][nf][2]), "+f"(c[mf][nf][3])
                        : "r"(af[mf][0]), "r"(af[mf][1]), "r"(af[mf][2]), "r"(af[mf][3]),
                          "r"(bf[nf][0]), "r"(bf[nf][1]));
                }
        }
        if (t + 1 < nk) stsAB(cur ^ 1, va, vb);
        __syncthreads();
    }

    // ---- epilogue: bias, store, BN stats ----
    float csum[4][2], csq[4][2];
#pragma unroll
    for (int nf = 0; nf < 4; nf++) {
        csum[nf][0] = csum[nf][1] = 0.f;
        csq[nf][0]  = csq[nf][1]  = 0.f;
    }
#pragma unroll
    for (int mf = 0; mf < 4; mf++) {
#pragma unroll
        for (int h = 0; h < 2; h++) {
            int r = row0 + m_base + mf * 16 + gid + h * 8;
            if (r >= M) continue;
#pragma unroll
            for (int nf = 0; nf < 4; nf++) {
                int col = n_base + nf * 8 + 2 * tig;
                if (col >= Nact) continue;
                float y0 = c[mf][nf][2 * h + 0] + __ldg(bias + col);
                float y1 = c[mf][nf][2 * h + 1] + __ldg(bias + col + 1);
                *(float2*)(C + (size_t)r * Nact + col) = make_float2(y0, y1);
                if (MODE == 1 || MODE == 2) {
                    csum[nf][0] += y0;  csum[nf][1] += y1;
                    csq[nf][0]  = fmaf(y0, y0, csq[nf][0]);
                    csq[nf][1]  = fmaf(y1, y1, csq[nf][1]);
                }
            }
        }
    }
    if (MODE == 1 || MODE == 2) {
#pragma unroll
        for (int nf = 0; nf < 4; nf++) {
            int col = n_base + nf * 8 + 2 * tig;
            atomicAdd(&sh_sum[col],     csum[nf][0]);
            atomicAdd(&sh_sum[col + 1], csum[nf][1]);
            atomicAdd(&sh_sq[col],      csq[nf][0]);
            atomicAdd(&sh_sq[col + 1],  csq[nf][1]);
        }
        __syncthreads();
        if (tid < 128) {
            float* st = (MODE == 1) ? g_stats : g_stats + 256;
            atomicAdd(&st[tid],       sh_sum[tid]);
            atomicAdd(&st[128 + tid], sh_sq[tid]);
        }
    }
}

// ---------------- launch ----------------
extern "C" void kernel_launch(void* const* d_in, const int* in_sizes, int n_in,
                              void* d_out, int out_size) {
    const float* h_V   = (const float*)d_in[0];
    const float* h_E   = (const float*)d_in[1];
    const float* rot   = (const float*)d_in[2];
    const float* trans = (const float*)d_in[3];
    const int*   eidx  = (const int*)  d_in[4];
    const float* W_va  = (const float*)d_in[5];
    const float* b_va  = (const float*)d_in[6];
    const float* W_vd  = (const float*)d_in[7];
    const float* b_vd  = (const float*)d_in[8];
    const float* W1    = (const float*)d_in[9];
    const float* b1    = (const float*)d_in[10];
    const float* g1    = (const float*)d_in[11];
    const float* be1   = (const float*)d_in[12];
    const float* W2    = (const float*)d_in[13];
    const float* b2    = (const float*)d_in[14];
    const float* g2    = (const float*)d_in[15];
    const float* be2   = (const float*)d_in[16];
    const float* W3    = (const float*)d_in[17];
    const float* b3    = (const float*)d_in[18];
    const float* Wm    = (const float*)d_in[19];
    const float* bm    = (const float*)d_in[20];

    int N = in_sizes[0] / HID;
    int E = in_sizes[1] / HID;
    float* out = (float*)d_out;

    float *pVl, *pVe, *pH, *pY1, *pY2, *pBfin, *pbfin;
    cudaGetSymbolAddress((void**)&pVl,   g_Vl);
    cudaGetSymbolAddress((void**)&pVe,   g_Ve);
    cudaGetSymbolAddress((void**)&pH,    g_H);
    cudaGetSymbolAddress((void**)&pY1,   g_Y1);
    cudaGetSymbolAddress((void**)&pY2,   g_Y2);
    cudaGetSymbolAddress((void**)&pBfin, g_Bfin);
    cudaGetSymbolAddress((void**)&pbfin, g_bfin);

    int gridN = (N + 127) / 128;
    int gridE = (E + 127) / 128;

    zero_stats_kernel<<<1, 512>>>();
    prep_final_kernel<<<129, 128>>>(W3, Wm, b3, bm);

    // projections (tf32 MMA)
    gemm_mma<0><<<gridN, 256>>>(h_V, nullptr, W_va, b_va, pVl, N, 128, 128, 96, HID);
    gemm_mma<0><<<gridE, 256>>>(h_E, nullptr, W_vd, b_vd, pVe, E, 128, 128, 96, HID);

    // geometric features (row-major H, padded to 448)
    edge_feat_kernel<<<(E + 7) / 8, 256>>>(pVe, pVl, eidx, rot, trans, pH, E);

    // MLP layer 1 (+ BN stats in epilogue)
    gemm_mma<1><<<gridE, 256>>>(pH, nullptr, W1, b1, pY1, E, DINP, 441, 128, DINP);
    bn_coef_kernel<<<1, 128>>>(0, g1, be1, 1.f / (float)E);

    // MLP layer 2 (BN+relu fused on A load, + BN stats)
    gemm_mma<2><<<gridE, 256>>>(pY1, nullptr, W2, b2, pY2, E, 128, 128, 128, HID);
    bn_coef_kernel<<<1, 128>>>(1, g2, be2, 1.f / (float)E);

    // fused layer3 + merge: [relu(bn(Y2)) | h_E] @ [W3@Wm_bot ; Wm_top] + bfin
    gemm_mma<3><<<gridE, 256>>>(pY2, h_E, pBfin, pbfin, out, E, 256, 256, 128, HID);
}

// round 12
// speedup vs baseline: 1.0013x; 1.0013x over previous
#include <cuda_runtime.h>
#include <math.h>
#include <stdint.h>

#define HID 128
#define NMAX 10000
#define EMAX 300000
#define DINP 448          // padded H width (441 -> 448)

// ---------------- device-global scratch (no allocs) ----------------
__device__ __align__(128) float g_Vl[(size_t)NMAX * 96];
__device__ __align__(128) float g_Ve[(size_t)EMAX * 96];
__device__ __align__(128) float g_H [(size_t)EMAX * DINP];
__device__ __align__(128) float g_Y1[(size_t)EMAX * HID];
__device__ __align__(128) float g_Y2[(size_t)EMAX * HID];
__device__ __align__(128) float g_Bfin[256 * 128];
__device__ __align__(128) float g_bfin[128];
__device__ float g_stats[512];   // layer {sum[128], sumsq[128]} x2
__device__ float g_coef [512];   // layer {a[128],   s[128]} x2

__device__ __forceinline__ float rtf32(float x) {
    uint32_t u;
    asm("cvt.rna.tf32.f32 %0, %1;" : "=r"(u) : "f"(x));
    return __uint_as_float(u);
}

// ---------------- small helpers ----------------
__global__ void zero_stats_kernel() {
    if (threadIdx.x < 512) g_stats[threadIdx.x] = 0.f;
}

__global__ void bn_coef_kernel(int layer, const float* __restrict__ g,
                               const float* __restrict__ be, float invM) {
    int c = threadIdx.x;
    float m = g_stats[layer * 256 + c] * invM;
    float v = g_stats[layer * 256 + 128 + c] * invM - m * m;
    float a = g[c] * rsqrtf(v + 1e-5f);
    g_coef[layer * 256 + c]       = a;
    g_coef[layer * 256 + 128 + c] = be[c] - m * a;
}

__global__ void prep_final_kernel(const float* __restrict__ W3, const float* __restrict__ Wm,
                                  const float* __restrict__ b3, const float* __restrict__ bm) {
    __shared__ float rowv[128];
    int j = threadIdx.x;
    int k = blockIdx.x;
    if (k < 128) {
        rowv[j] = W3[k * 128 + j];
        __syncthreads();
        float s = 0.f;
#pragma unroll 8
        for (int t = 0; t < 128; t++) s += rowv[t] * Wm[(128 + t) * 128 + j];
        g_Bfin[k * 128 + j]         = s;                 // W3 @ Wm_bot
        g_Bfin[(128 + k) * 128 + j] = Wm[k * 128 + j];   // Wm_top
    } else {
        rowv[j] = b3[j];
        __syncthreads();
        float s = 0.f;
#pragma unroll 8
        for (int t = 0; t < 128; t++) s += rowv[t] * Wm[(128 + t) * 128 + j];
        g_bfin[j] = s + bm[j];
    }
}

// ---------------- per-edge geometric features (one warp per edge) ----------------
__global__ void edge_feat_kernel(const float* __restrict__ Ve, const float* __restrict__ Vl,
                                 const int* __restrict__ eidx, const float* __restrict__ rot,
                                 const float* __restrict__ trans, float* __restrict__ H, int E) {
    int w    = (blockIdx.x * blockDim.x + threadIdx.x) >> 5;
    int lane = threadIdx.x & 31;
    if (w >= E) return;
    const size_t e = (size_t)w;

    int s = eidx[e];
    int d = eidx[(size_t)E + e];

    float R0 = __ldg(rot + e * 9 + 0), R1 = __ldg(rot + e * 9 + 1), R2 = __ldg(rot + e * 9 + 2);
    float R3 = __ldg(rot + e * 9 + 3), R4 = __ldg(rot + e * 9 + 4), R5 = __ldg(rot + e * 9 + 5);
    float R6 = __ldg(rot + e * 9 + 6), R7 = __ldg(rot + e * 9 + 7), R8 = __ldg(rot + e * 9 + 8);
    float t0 = __ldg(trans + e * 3 + 0), t1 = __ldg(trans + e * 3 + 1), t2 = __ldg(trans + e * 3 + 2);

    const float* ve = Ve + e * 96 + lane * 3;
    float ve0 = ve[0], ve1 = ve[1], ve2 = ve[2];
    const float* vs = Vl + (size_t)s * 96 + lane * 3;
    float vs0 = vs[0], vs1 = vs[1], vs2 = vs[2];
    const float* vd = Vl + (size_t)d * 96 + lane * 3;
    float vd0 = vd[0], vd1 = vd[1], vd2 = vd[2];

    float* h = H + e * (size_t)DINP;
    h[lane * 3 + 0] = ve0;  h[lane * 3 + 1] = ve1;  h[lane * 3 + 2] = ve2;
    h[96 + lane * 3 + 0] = vs0;  h[96 + lane * 3 + 1] = vs1;  h[96 + lane * 3 + 2] = vs2;
    h[192 + lane * 3 + 0] = R0 * ve0 + R1 * ve1 + R2 * ve2 + t0;
    h[192 + lane * 3 + 1] = R3 * ve0 + R4 * ve1 + R5 * ve2 + t1;
    h[192 + lane * 3 + 2] = R6 * ve0 + R7 * ve1 + R8 * ve2 + t2;
    float rs0 = R0 * vs0 + R1 * vs1 + R2 * vs2;
    float rs1 = R3 * vs0 + R4 * vs1 + R5 * vs2;
    float rs2 = R6 * vs0 + R7 * vs1 + R8 * vs2;
    h[288 + lane * 3 + 0] = rs0 + t0;
    h[288 + lane * 3 + 1] = rs1 + t1;
    h[288 + lane * 3 + 2] = rs2 + t2;
    h[409 + lane] = vd0 * rs0 + vd1 * rs1 + vd2 * rs2;
    if (lane < 9) h[384 + lane] = __ldg(rot + e * 9 + lane);
    if (lane < 16) {
        float nrm = sqrtf(t0 * t0 + t1 * t1 + t2 * t2);
        float c = (50.f / 15.f) * (float)lane;
        float z = (nrm - c) * (1.f / 3.125f);
        h[393 + lane] = expf(-z * z);
    }
    if (lane < 7) h[441 + lane] = 0.f;   // pad to 448
}

// ---------------- tf32 mma.sync GEMM: 128x128x16 tile, 8 warps, double-buffered ----------------
// MODE 0: C = A@B + bias                                        (projections)
// MODE 1: C = A@B + bias, + BN stats layer0                     (GEMM1, A=H padded)
// MODE 2: C = relu(a0*A+s0)@B + bias, + BN stats layer1         (GEMM2, A=Y1)
// MODE 3: C = [relu(a1*A+s1) | A2]@B + bias                     (final, A=Y2, A2=h_E)
template <int MODE>
__global__ void __launch_bounds__(256, 2)
gemm_mma(const float* __restrict__ A, const float* __restrict__ A2,
         const float* __restrict__ B, const float* __restrict__ bias,
         float* __restrict__ C, int M, int K, int KB, int Nact, int lda) {
    __shared__ float As[2][128][20];
    __shared__ float Bs[2][16][136];
    __shared__ float sh_sum[128];
    __shared__ float sh_sq[128];
    __shared__ float s_coef[256];

    const int tid  = threadIdx.x;
    const int wid  = tid >> 5;
    const int lane = tid & 31;
    const int gid  = lane >> 2;   // group id 0..7
    const int tig  = lane & 3;    // thread-in-group 0..3
    const int row0 = blockIdx.x * 128;
    const int m_base = (wid >> 2) * 64;   // 0 or 64
    const int n_base = (wid & 3) * 32;    // 0,32,64,96

    if (MODE == 1 || MODE == 2) {
        if (tid < 128) { sh_sum[tid] = 0.f; sh_sq[tid] = 0.f; }
    }
    if (MODE >= 2) {
        const float* cf = g_coef + ((MODE == 2) ? 0 : 256);
        if (tid < 256) s_coef[tid] = cf[tid];
    }
    // REQUIRED: loadA below reads s_coef written by other threads (MODE>=2).
    __syncthreads();

    auto loadA = [&](int k0, float4 va[2]) {
#pragma unroll
        for (int j = 0; j < 2; j++) {
            int idx = tid + 256 * j;
            int r = idx >> 2, kq = idx & 3;
            int k = k0 + kq * 4;
            int grow = row0 + r;
            float4 v = make_float4(0.f, 0.f, 0.f, 0.f);
            if (grow < M) {
                if (MODE == 3 && k >= 128) {
                    v = *(const float4*)(A2 + (size_t)grow * 128 + (k - 128));
                } else {
                    v = *(const float4*)(A + (size_t)grow * lda + k);
                    if (MODE >= 2) {
                        v.x = fmaxf(fmaf(s_coef[k + 0], v.x, s_coef[128 + k + 0]), 0.f);
                        v.y = fmaxf(fmaf(s_coef[k + 1], v.y, s_coef[128 + k + 1]), 0.f);
                        v.z = fmaxf(fmaf(s_coef[k + 2], v.z, s_coef[128 + k + 2]), 0.f);
                        v.w = fmaxf(fmaf(s_coef[k + 3], v.w, s_coef[128 + k + 3]), 0.f);
                    }
                }
            }
            v.x = rtf32(v.x); v.y = rtf32(v.y); v.z = rtf32(v.z); v.w = rtf32(v.w);
            va[j] = v;
        }
    };
    auto loadB = [&](int k0, float4 vb[2]) {
#pragma unroll
        for (int j = 0; j < 2; j++) {
            int idx = tid + 256 * j;
            int kr = idx >> 5, nq = idx & 31;
            int k = k0 + kr;
            int n = nq * 4;
            float4 v = make_float4(0.f, 0.f, 0.f, 0.f);
            if (k < KB && n < Nact)
                v = *(const float4*)(B + (size_t)k * Nact + n);
            v.x = rtf32(v.x); v.y = rtf32(v.y); v.z = rtf32(v.z); v.w = rtf32(v.w);
            vb[j] = v;
        }
    };
    auto stsAB = [&](int buf, const float4 va[2], const float4 vb[2]) {
#pragma unroll
        for (int j = 0; j < 2; j++) {
            int idx = tid + 256 * j;
            *(float4*)&As[buf][idx >> 2][(idx & 3) * 4] = va[j];
            *(float4*)&Bs[buf][idx >> 5][(idx & 31) * 4] = vb[j];
        }
    };

    float c[4][4][4];
#pragma unroll
    for (int mf = 0; mf < 4; mf++)
#pragma unroll
        for (int nf = 0; nf < 4; nf++)
#pragma unroll
            for (int j = 0; j < 4; j++) c[mf][nf][j] = 0.f;

    const int nk = K >> 4;
    float4 va[2], vb[2];
    loadA(0, va);
    loadB(0, vb);
    stsAB(0, va, vb);
    __syncthreads();

    for (int t = 0; t < nk; t++) {
        const int cur = t & 1;
        if (t + 1 < nk) {
            loadA((t + 1) << 4, va);
            loadB((t + 1) << 4, vb);
        }
        // ---- mma on buffer cur: two k=8 halves ----
#pragma unroll
        for (int kk = 0; kk < 16; kk += 8) {
            uint32_t af[4][4];
#pragma unroll
            for (int mf = 0; mf < 4; mf++) {
                int mr = m_base + mf * 16 + gid;
                af[mf][0] = __float_as_uint(As[cur][mr    ][kk + tig    ]);
                af[mf][1] = __float_as_uint(As[cur][mr + 8][kk + tig    ]);
                af[mf][2] = __float_as_uint(As[cur][mr    ][kk + tig + 4]);
                af[mf][3] = __float_as_uint(As[cur][mr + 8][kk + tig + 4]);
            }
            uint32_t bf[4][2];
#pragma unroll
            for (int nf = 0; nf < 4; nf++) {
                int nc = n_base + nf * 8 + gid;
                bf[nf][0] = __float_as_uint(Bs[cur][kk + tig    ][nc]);
                bf[nf][1] = __float_as_uint(Bs[cur][kk + tig + 4][nc]);
            }
#pragma unroll
            for (int mf = 0; mf < 4; mf++)
#pragma unroll
                for (int nf = 0; nf < 4; nf++) {
                    asm volatile(
                        "mma.sync.aligned.m16n8k8.row.col.f32.tf32.tf32.f32 "
                        "{%0,%1,%2,%3}, {%4,%5,%6,%7}, {%8,%9}, {%0,%1,%2,%3};"
                        : "+f"(c[mf][nf][0]), "+f"(c[mf][nf][1]),
                          "+f"(c[mf][nf][2]), "+f"(c[mf][nf][3])
                        : "r"(af[mf][0]), "r"(af[mf][1]), "r"(af[mf][2]), "r"(af[mf][3]),
                          "r"(bf[nf][0]), "r"(bf[nf][1]));
                }
        }
        if (t + 1 < nk) stsAB(cur ^ 1, va, vb);
        __syncthreads();
    }

    // ---- epilogue: bias, store, BN stats ----
    float csum[4][2], csq[4][2];
#pragma unroll
    for (int nf = 0; nf < 4; nf++) {
        csum[nf][0] = csum[nf][1] = 0.f;
        csq[nf][0]  = csq[nf][1]  = 0.f;
    }
#pragma unroll
    for (int mf = 0; mf < 4; mf++) {
#pragma unroll
        for (int h = 0; h < 2; h++) {
            int r = row0 + m_base + mf * 16 + gid + h * 8;
            if (r >= M) continue;
#pragma unroll
            for (int nf = 0; nf < 4; nf++) {
                int col = n_base + nf * 8 + 2 * tig;
                if (col >= Nact) continue;
                float y0 = c[mf][nf][2 * h + 0] + __ldg(bias + col);
                float y1 = c[mf][nf][2 * h + 1] + __ldg(bias + col + 1);
                *(float2*)(C + (size_t)r * Nact + col) = make_float2(y0, y1);
                if (MODE == 1 || MODE == 2) {
                    csum[nf][0] += y0;  csum[nf][1] += y1;
                    csq[nf][0]  = fmaf(y0, y0, csq[nf][0]);
                    csq[nf][1]  = fmaf(y1, y1, csq[nf][1]);
                }
            }
        }
    }
    if (MODE == 1 || MODE == 2) {
#pragma unroll
        for (int nf = 0; nf < 4; nf++) {
            int col = n_base + nf * 8 + 2 * tig;
            atomicAdd(&sh_sum[col],     csum[nf][0]);
            atomicAdd(&sh_sum[col + 1], csum[nf][1]);
            atomicAdd(&sh_sq[col],      csq[nf][0]);
            atomicAdd(&sh_sq[col + 1],  csq[nf][1]);
        }
        __syncthreads();
        if (tid < 128) {
            float* st = (MODE == 1) ? g_stats : g_stats + 256;
            atomicAdd(&st[tid],       sh_sum[tid]);
            atomicAdd(&st[128 + tid], sh_sq[tid]);
        }
    }
}

// ---------------- launch ----------------
extern "C" void kernel_launch(void* const* d_in, const int* in_sizes, int n_in,
                              void* d_out, int out_size) {
    const float* h_V   = (const float*)d_in[0];
    const float* h_E   = (const float*)d_in[1];
    const float* rot   = (const float*)d_in[2];
    const float* trans = (const float*)d_in[3];
    const int*   eidx  = (const int*)  d_in[4];
    const float* W_va  = (const float*)d_in[5];
    const float* b_va  = (const float*)d_in[6];
    const float* W_vd  = (const float*)d_in[7];
    const float* b_vd  = (const float*)d_in[8];
    const float* W1    = (const float*)d_in[9];
    const float* b1    = (const float*)d_in[10];
    const float* g1    = (const float*)d_in[11];
    const float* be1   = (const float*)d_in[12];
    const float* W2    = (const float*)d_in[13];
    const float* b2    = (const float*)d_in[14];
    const float* g2    = (const float*)d_in[15];
    const float* be2   = (const float*)d_in[16];
    const float* W3    = (const float*)d_in[17];
    const float* b3    = (const float*)d_in[18];
    const float* Wm    = (const float*)d_in[19];
    const float* bm    = (const float*)d_in[20];

    int N = in_sizes[0] / HID;
    int E = in_sizes[1] / HID;
    float* out = (float*)d_out;

    float *pVl, *pVe, *pH, *pY1, *pY2, *pBfin, *pbfin;
    cudaGetSymbolAddress((void**)&pVl,   g_Vl);
    cudaGetSymbolAddress((void**)&pVe,   g_Ve);
    cudaGetSymbolAddress((void**)&pH,    g_H);
    cudaGetSymbolAddress((void**)&pY1,   g_Y1);
    cudaGetSymbolAddress((void**)&pY2,   g_Y2);
    cudaGetSymbolAddress((void**)&pBfin, g_Bfin);
    cudaGetSymbolAddress((void**)&pbfin, g_bfin);

    int gridN = (N + 127) / 128;
    int gridE = (E + 127) / 128;

    zero_stats_kernel<<<1, 512>>>();
    prep_final_kernel<<<129, 128>>>(W3, Wm, b3, bm);

    // projections (tf32 MMA)
    gemm_mma<0><<<gridN, 256>>>(h_V, nullptr, W_va, b_va, pVl, N, 128, 128, 96, HID);
    gemm_mma<0><<<gridE, 256>>>(h_E, nullptr, W_vd, b_vd, pVe, E, 128, 128, 96, HID);

    // geometric features (row-major H, padded to 448)
    edge_feat_kernel<<<(E + 7) / 8, 256>>>(pVe, pVl, eidx, rot, trans, pH, E);

    // MLP layer 1 (+ BN stats in epilogue)
    gemm_mma<1><<<gridE, 256>>>(pH, nullptr, W1, b1, pY1, E, DINP, 441, 128, DINP);
    bn_coef_kernel<<<1, 128>>>(0, g1, be1, 1.f / (float)E);

    // MLP layer 2 (BN+relu fused on A load, + BN stats)
    gemm_mma<2><<<gridE, 256>>>(pY1, nullptr, W2, b2, pY2, E, 128, 128, 128, HID);
    bn_coef_kernel<<<1, 128>>>(1, g2, be2, 1.f / (float)E);

    // fused layer3 + merge: [relu(bn(Y2)) | h_E] @ [W3@Wm_bot ; Wm_top] + bfin
    gemm_mma<3><<<gridE, 256>>>(pY2, h_E, pBfin, pbfin, out, E, 256, 256, 128, HID);
}

// round 13
// speedup vs baseline: 1.0018x; 1.0005x over previous
#include <cuda_runtime.h>
#include <math.h>
#include <stdint.h>

#define HID 128
#define NMAX 10000
#define EMAX 300000
#define DINP 448          // padded H width (441 -> 448)

// ---------------- device-global scratch (no allocs) ----------------
__device__ __align__(128) float g_Vl[(size_t)NMAX * 96];
__device__ __align__(128) float g_Ve[(size_t)EMAX * 96];
__device__ __align__(128) float g_H [(size_t)EMAX * DINP];
__device__ __align__(128) float g_Y1[(size_t)EMAX * HID];
__device__ __align__(128) float g_Y2[(size_t)EMAX * HID];
__device__ __align__(128) float g_Bfin[256 * 128];
__device__ __align__(128) float g_bfin[128];
__device__ float g_stats[512];   // layer {sum[128], sumsq[128]} x2
__device__ float g_coef [512];   // layer {a[128],   s[128]} x2

__device__ __forceinline__ float rtf32(float x) {
    uint32_t u;
    asm("cvt.rna.tf32.f32 %0, %1;" : "=r"(u) : "f"(x));
    return __uint_as_float(u);
}

// ---------------- small helpers ----------------
__global__ void zero_stats_kernel() {
    if (threadIdx.x < 512) g_stats[threadIdx.x] = 0.f;
}

__global__ void bn_coef_kernel(int layer, const float* __restrict__ g,
                               const float* __restrict__ be, float invM) {
    int c = threadIdx.x;
    float m = g_stats[layer * 256 + c] * invM;
    float v = g_stats[layer * 256 + 128 + c] * invM - m * m;
    float a = g[c] * rsqrtf(v + 1e-5f);
    g_coef[layer * 256 + c]       = a;
    g_coef[layer * 256 + 128 + c] = be[c] - m * a;
}

__global__ void prep_final_kernel(const float* __restrict__ W3, const float* __restrict__ Wm,
                                  const float* __restrict__ b3, const float* __restrict__ bm) {
    __shared__ float rowv[128];
    int j = threadIdx.x;
    int k = blockIdx.x;
    if (k < 128) {
        rowv[j] = W3[k * 128 + j];
        __syncthreads();
        float s = 0.f;
#pragma unroll 8
        for (int t = 0; t < 128; t++) s += rowv[t] * Wm[(128 + t) * 128 + j];
        g_Bfin[k * 128 + j]         = s;                 // W3 @ Wm_bot
        g_Bfin[(128 + k) * 128 + j] = Wm[k * 128 + j];   // Wm_top
    } else {
        rowv[j] = b3[j];
        __syncthreads();
        float s = 0.f;
#pragma unroll 8
        for (int t = 0; t < 128; t++) s += rowv[t] * Wm[(128 + t) * 128 + j];
        g_bfin[j] = s + bm[j];
    }
}

// ---------------- per-edge geometric features (one warp per edge) ----------------
__global__ void edge_feat_kernel(const float* __restrict__ Ve, const float* __restrict__ Vl,
                                 const int* __restrict__ eidx, const float* __restrict__ rot,
                                 const float* __restrict__ trans, float* __restrict__ H, int E) {
    int w    = (blockIdx.x * blockDim.x + threadIdx.x) >> 5;
    int lane = threadIdx.x & 31;
    if (w >= E) return;
    const size_t e = (size_t)w;

    int s = eidx[e];
    int d = eidx[(size_t)E + e];

    float R0 = __ldg(rot + e * 9 + 0), R1 = __ldg(rot + e * 9 + 1), R2 = __ldg(rot + e * 9 + 2);
    float R3 = __ldg(rot + e * 9 + 3), R4 = __ldg(rot + e * 9 + 4), R5 = __ldg(rot + e * 9 + 5);
    float R6 = __ldg(rot + e * 9 + 6), R7 = __ldg(rot + e * 9 + 7), R8 = __ldg(rot + e * 9 + 8);
    float t0 = __ldg(trans + e * 3 + 0), t1 = __ldg(trans + e * 3 + 1), t2 = __ldg(trans + e * 3 + 2);

    const float* ve = Ve + e * 96 + lane * 3;
    float ve0 = ve[0], ve1 = ve[1], ve2 = ve[2];
    const float* vs = Vl + (size_t)s * 96 + lane * 3;
    float vs0 = vs[0], vs1 = vs[1], vs2 = vs[2];
    const float* vd = Vl + (size_t)d * 96 + lane * 3;
    float vd0 = vd[0], vd1 = vd[1], vd2 = vd[2];

    float* h = H + e * (size_t)DINP;
    h[lane * 3 + 0] = ve0;  h[lane * 3 + 1] = ve1;  h[lane * 3 + 2] = ve2;
    h[96 + lane * 3 + 0] = vs0;  h[96 + lane * 3 + 1] = vs1;  h[96 + lane * 3 + 2] = vs2;
    h[192 + lane * 3 + 0] = R0 * ve0 + R1 * ve1 + R2 * ve2 + t0;
    h[192 + lane * 3 + 1] = R3 * ve0 + R4 * ve1 + R5 * ve2 + t1;
    h[192 + lane * 3 + 2] = R6 * ve0 + R7 * ve1 + R8 * ve2 + t2;
    float rs0 = R0 * vs0 + R1 * vs1 + R2 * vs2;
    float rs1 = R3 * vs0 + R4 * vs1 + R5 * vs2;
    float rs2 = R6 * vs0 + R7 * vs1 + R8 * vs2;
    h[288 + lane * 3 + 0] = rs0 + t0;
    h[288 + lane * 3 + 1] = rs1 + t1;
    h[288 + lane * 3 + 2] = rs2 + t2;
    h[409 + lane] = vd0 * rs0 + vd1 * rs1 + vd2 * rs2;
    if (lane < 9) h[384 + lane] = __ldg(rot + e * 9 + lane);
    if (lane < 16) {
        float nrm = sqrtf(t0 * t0 + t1 * t1 + t2 * t2);
        float c = (50.f / 15.f) * (float)lane;
        float z = (nrm - c) * (1.f / 3.125f);
        h[393 + lane] = expf(-z * z);
    }
    if (lane < 7) h[441 + lane] = 0.f;   // pad to 448
}

// ---------------- tf32 mma.sync GEMM: 128x128x16 tile, 8 warps, double-buffered ----------------
// MODE 0: C = A@B + bias                                        (projections)
// MODE 1: C = A@B + bias, + BN stats layer0                     (GEMM1, A=H padded)
// MODE 2: C = relu(a0*A+s0)@B + bias, + BN stats layer1         (GEMM2, A=Y1)
// MODE 3: C = [relu(a1*A+s1) | A2]@B + bias                     (final, A=Y2, A2=h_E)
template <int MODE>
__global__ void __launch_bounds__(256, 2)
gemm_mma(const float* __restrict__ A, const float* __restrict__ A2,
         const float* __restrict__ B, const float* __restrict__ bias,
         float* __restrict__ C, int M, int K, int KB, int Nact, int lda) {
    __shared__ float As[2][128][20];
    __shared__ float Bs[2][16][136];
    __shared__ float sh_sum[128];
    __shared__ float sh_sq[128];
    __shared__ float s_coef[256];

    const int tid  = threadIdx.x;
    const int wid  = tid >> 5;
    const int lane = tid & 31;
    const int gid  = lane >> 2;   // group id 0..7
    const int tig  = lane & 3;    // thread-in-group 0..3
    const int row0 = blockIdx.x * 128;
    const int m_base = (wid >> 2) * 64;   // 0 or 64
    const int n_base = (wid & 3) * 32;    // 0,32,64,96

    if (MODE == 1 || MODE == 2) {
        if (tid < 128) { sh_sum[tid] = 0.f; sh_sq[tid] = 0.f; }
    }
    if (MODE >= 2) {
        const float* cf = g_coef + ((MODE == 2) ? 0 : 256);
        if (tid < 256) s_coef[tid] = cf[tid];
    }
    // REQUIRED: loadA below reads s_coef written by other threads (MODE>=2).
    __syncthreads();

    auto loadA = [&](int k0, float4 va[2]) {
#pragma unroll
        for (int j = 0; j < 2; j++) {
            int idx = tid + 256 * j;
            int r = idx >> 2, kq = idx & 3;
            int k = k0 + kq * 4;
            int grow = row0 + r;
            float4 v = make_float4(0.f, 0.f, 0.f, 0.f);
            if (grow < M) {
                if (MODE == 3 && k >= 128) {
                    v = *(const float4*)(A2 + (size_t)grow * 128 + (k - 128));
                } else {
                    v = *(const float4*)(A + (size_t)grow * lda + k);
                    if (MODE >= 2) {
                        v.x = fmaxf(fmaf(s_coef[k + 0], v.x, s_coef[128 + k + 0]), 0.f);
                        v.y = fmaxf(fmaf(s_coef[k + 1], v.y, s_coef[128 + k + 1]), 0.f);
                        v.z = fmaxf(fmaf(s_coef[k + 2], v.z, s_coef[128 + k + 2]), 0.f);
                        v.w = fmaxf(fmaf(s_coef[k + 3], v.w, s_coef[128 + k + 3]), 0.f);
                    }
                }
            }
            v.x = rtf32(v.x); v.y = rtf32(v.y); v.z = rtf32(v.z); v.w = rtf32(v.w);
            va[j] = v;
        }
    };
    auto loadB = [&](int k0, float4 vb[2]) {
#pragma unroll
        for (int j = 0; j < 2; j++) {
            int idx = tid + 256 * j;
            int kr = idx >> 5, nq = idx & 31;
            int k = k0 + kr;
            int n = nq * 4;
            float4 v = make_float4(0.f, 0.f, 0.f, 0.f);
            if (k < KB && n < Nact)
                v = *(const float4*)(B + (size_t)k * Nact + n);
            v.x = rtf32(v.x); v.y = rtf32(v.y); v.z = rtf32(v.z); v.w = rtf32(v.w);
            vb[j] = v;
        }
    };
    auto stsAB = [&](int buf, const float4 va[2], const float4 vb[2]) {
#pragma unroll
        for (int j = 0; j < 2; j++) {
            int idx = tid + 256 * j;
            *(float4*)&As[buf][idx >> 2][(idx & 3) * 4] = va[j];
            *(float4*)&Bs[buf][idx >> 5][(idx & 31) * 4] = vb[j];
        }
    };

    float c[4][4][4];
#pragma unroll
    for (int mf = 0; mf < 4; mf++)
#pragma unroll
        for (int nf = 0; nf < 4; nf++)
#pragma unroll
            for (int j = 0; j < 4; j++) c[mf][nf][j] = 0.f;

    const int nk = K >> 4;
    float4 va[2], vb[2];
    loadA(0, va);
    loadB(0, vb);
    stsAB(0, va, vb);
    __syncthreads();

    for (int t = 0; t < nk; t++) {
        const int cur = t & 1;
        if (t + 1 < nk) {
            loadA((t + 1) << 4, va);
            loadB((t + 1) << 4, vb);
        }
        // ---- mma on buffer cur: two k=8 halves ----
#pragma unroll
        for (int kk = 0; kk < 16; kk += 8) {
            uint32_t af[4][4];
#pragma unroll
            for (int mf = 0; mf < 4; mf++) {
                int mr = m_base + mf * 16 + gid;
                af[mf][0] = __float_as_uint(As[cur][mr    ][kk + tig    ]);
                af[mf][1] = __float_as_uint(As[cur][mr + 8][kk + tig    ]);
                af[mf][2] = __float_as_uint(As[cur][mr    ][kk + tig + 4]);
                af[mf][3] = __float_as_uint(As[cur][mr + 8][kk + tig + 4]);
            }
            uint32_t bf[4][2];
#pragma unroll
            for (int nf = 0; nf < 4; nf++) {
                int nc = n_base + nf * 8 + gid;
                bf[nf][0] = __float_as_uint(Bs[cur][kk + tig    ][nc]);
                bf[nf][1] = __float_as_uint(Bs[cur][kk + tig + 4][nc]);
            }
#pragma unroll
            for (int mf = 0; mf < 4; mf++)
#pragma unroll
                for (int nf = 0; nf < 4; nf++) {
                    asm volatile(
                        "mma.sync.aligned.m16n8k8.row.col.f32.tf32.tf32.f32 "
                        "{%0,%1,%2,%3}, {%4,%5,%6,%7}, {%8,%9}, {%0,%1,%2,%3};"
                        : "+f"(c[mf][nf][0]), "+f"(c[mf][nf][1]),
                          "+f"(c[mf][nf][2]), "+f"(c[mf][nf][3])
                        : "r"(af[mf][0]), "r"(af[mf][1]), "r"(af[mf][2]), "r"(af[mf][3]),
                          "r"(bf[nf][0]), "r"(bf[nf][1]));
                }
        }
        if (t + 1 < nk) stsAB(cur ^ 1, va, vb);
        __syncthreads();
    }

    // ---- epilogue: bias, store, BN stats ----
    float csum[4][2], csq[4][2];
#pragma unroll
    for (int nf = 0; nf < 4; nf++) {
        csum[nf][0] = csum[nf][1] = 0.f;
        csq[nf][0]  = csq[nf][1]  = 0.f;
    }
#pragma unroll
    for (int mf = 0; mf < 4; mf++) {
#pragma unroll
        for (int h = 0; h < 2; h++) {
            int r = row0 + m_base + mf * 16 + gid + h * 8;
            if (r >= M) continue;
#pragma unroll
            for (int nf = 0; nf < 4; nf++) {
                int col = n_base + nf * 8 + 2 * tig;
                if (col >= Nact) continue;
                float y0 = c[mf][nf][2 * h + 0] + __ldg(bias + col);
                float y1 = c[mf][nf][2 * h + 1] + __ldg(bias + col + 1);
                *(float2*)(C + (size_t)r * Nact + col) = make_float2(y0, y1);
                if (MODE == 1 || MODE == 2) {
                    csum[nf][0] += y0;  csum[nf][1] += y1;
                    csq[nf][0]  = fmaf(y0, y0, csq[nf][0]);
                    csq[nf][1]  = fmaf(y1, y1, csq[nf][1]);
                }
            }
        }
    }
    if (MODE == 1 || MODE == 2) {
#pragma unroll
        for (int nf = 0; nf < 4; nf++) {
            int col = n_base + nf * 8 + 2 * tig;
            atomicAdd(&sh_sum[col],     csum[nf][0]);
            atomicAdd(&sh_sum[col + 1], csum[nf][1]);
            atomicAdd(&sh_sq[col],      csq[nf][0]);
            atomicAdd(&sh_sq[col + 1],  csq[nf][1]);
        }
        __syncthreads();
        if (tid < 128) {
            float* st = (MODE == 1) ? g_stats : g_stats + 256;
            atomicAdd(&st[tid],       sh_sum[tid]);
            atomicAdd(&st[128 + tid], sh_sq[tid]);
        }
    }
}

// ---------------- launch ----------------
extern "C" void kernel_launch(void* const* d_in, const int* in_sizes, int n_in,
                              void* d_out, int out_size) {
    const float* h_V   = (const float*)d_in[0];
    const float* h_E   = (const float*)d_in[1];
    const float* rot   = (const float*)d_in[2];
    const float* trans = (const float*)d_in[3];
    const int*   eidx  = (const int*)  d_in[4];
    const float* W_va  = (const float*)d_in[5];
    const float* b_va  = (const float*)d_in[6];
    const float* W_vd  = (const float*)d_in[7];
    const float* b_vd  = (const float*)d_in[8];
    const float* W1    = (const float*)d_in[9];
    const float* b1    = (const float*)d_in[10];
    const float* g1    = (const float*)d_in[11];
    const float* be1   = (const float*)d_in[12];
    const float* W2    = (const float*)d_in[13];
    const float* b2    = (const float*)d_in[14];
    const float* g2    = (const float*)d_in[15];
    const float* be2   = (const float*)d_in[16];
    const float* W3    = (const float*)d_in[17];
    const float* b3    = (const float*)d_in[18];
    const float* Wm    = (const float*)d_in[19];
    const float* bm    = (const float*)d_in[20];

    int N = in_sizes[0] / HID;
    int E = in_sizes[1] / HID;
    float* out = (float*)d_out;

    float *pVl, *pVe, *pH, *pY1, *pY2, *pBfin, *pbfin;
    cudaGetSymbolAddress((void**)&pVl,   g_Vl);
    cudaGetSymbolAddress((void**)&pVe,   g_Ve);
    cudaGetSymbolAddress((void**)&pH,    g_H);
    cudaGetSymbolAddress((void**)&pY1,   g_Y1);
    cudaGetSymbolAddress((void**)&pY2,   g_Y2);
    cudaGetSymbolAddress((void**)&pBfin, g_Bfin);
    cudaGetSymbolAddress((void**)&pbfin, g_bfin);

    int gridN = (N + 127) / 128;
    int gridE = (E + 127) / 128;

    zero_stats_kernel<<<1, 512>>>();
    prep_final_kernel<<<129, 128>>>(W3, Wm, b3, bm);

    // projections (tf32 MMA)
    gemm_mma<0><<<gridN, 256>>>(h_V, nullptr, W_va, b_va, pVl, N, 128, 128, 96, HID);
    gemm_mma<0><<<gridE, 256>>>(h_E, nullptr, W_vd, b_vd, pVe, E, 128, 128, 96, HID);

    // geometric features (row-major H, padded to 448)
    edge_feat_kernel<<<(E + 7) / 8, 256>>>(pVe, pVl, eidx, rot, trans, pH, E);

    // MLP layer 1 (+ BN stats in epilogue)
    gemm_mma<1><<<gridE, 256>>>(pH, nullptr, W1, b1, pY1, E, DINP, 441, 128, DINP);
    bn_coef_kernel<<<1, 128>>>(0, g1, be1, 1.f / (float)E);

    // MLP layer 2 (BN+relu fused on A load, + BN stats)
    gemm_mma<2><<<gridE, 256>>>(pY1, nullptr, W2, b2, pY2, E, 128, 128, 128, HID);
    bn_coef_kernel<<<1, 128>>>(1, g2, be2, 1.f / (float)E);

    // fused layer3 + merge: [relu(bn(Y2)) | h_E] @ [W3@Wm_bot ; Wm_top] + bfin
    gemm_mma<3><<<gridE, 256>>>(pY2, h_E, pBfin, pbfin, out, E, 256, 256, 128, HID);
}